// round 1
// baseline (speedup 1.0000x reference)
#include <cuda_runtime.h>
#include <cuda_bf16.h>

// Problem constants (fixed by the reference)
#define Nn 2048
#define Mm 10
#define Dd 256
#define ROWS (Nn * Mm)   // 20480

// Scratch (device globals — no allocation allowed in kernel_launch)
__device__ float g_embn[(size_t)ROWS * Dd];   // normalized embeddings (20480 x 256)
__device__ float g_cent[(size_t)Nn * Dd];     // normalized centroids  (2048 x 256)
__device__ float g_rowsum[ROWS];              // per-(n,m) sum of exp(sim - shift)
__device__ float g_pos[ROWS];                 // per-(n,m) sim[n,m,n]

// ---------------------------------------------------------------------------
// Kernel 1: per-speaker prep. One block per n (2048 blocks), 256 threads (=D).
// Computes centroid[n] = l2norm(sum_m emb[n,m]) and emb_norm rows, zeroes rowsum.
// ---------------------------------------------------------------------------
__global__ void prep_kernel(const float* __restrict__ emb) {
    int n = blockIdx.x;
    int d = threadIdx.x;
    __shared__ float red[256];
    __shared__ float nrm;

    float v[Mm];
    float s = 0.f;
#pragma unroll
    for (int m = 0; m < Mm; m++) {
        v[m] = emb[((size_t)n * Mm + m) * Dd + d];
        s += v[m];
    }

    // centroid norm = ||sum_m emb||  (l2norm invariant to the 1/M scale)
    red[d] = s * s;
    __syncthreads();
    for (int off = 128; off > 0; off >>= 1) {
        if (d < off) red[d] += red[d + off];
        __syncthreads();
    }
    if (d == 0) nrm = fmaxf(sqrtf(red[0]), 1e-12f);
    __syncthreads();
    g_cent[(size_t)n * Dd + d] = s / nrm;

    // per-utterance norms
#pragma unroll
    for (int m = 0; m < Mm; m++) {
        __syncthreads();
        red[d] = v[m] * v[m];
        __syncthreads();
        for (int off = 128; off > 0; off >>= 1) {
            if (d < off) red[d] += red[d + off];
            __syncthreads();
        }
        if (d == 0) nrm = fmaxf(sqrtf(red[0]), 1e-12f);
        __syncthreads();
        g_embn[((size_t)n * Mm + m) * Dd + d] = v[m] / nrm;
    }

    // zero row accumulators for this speaker's M rows (graph-replay safe)
    if (d < Mm) g_rowsum[n * Mm + d] = 0.f;
}

// ---------------------------------------------------------------------------
// Kernel 2: fused GEMM + logsumexp partials.
// C tile 128x128, BK=8, 256 threads, 8x8 microtile per thread.
// sim = |w| * (embn . cent) + b; since cos<=1, shift = |w|+b bounds sim,
// so exp(sim - shift) never overflows -> single pass, no max scan.
// ---------------------------------------------------------------------------
__global__ void __launch_bounds__(256, 2)
gemm_lse_kernel(const float* __restrict__ wp, const float* __restrict__ bp) {
    constexpr int BM = 128, BN = 128, BK = 8, TM = 8, TN = 8;
    __shared__ float As[BK][BM];
    __shared__ float Bs[BK][BN];

    const int r0 = blockIdx.y * BM;   // row tile (0..159)
    const int c0 = blockIdx.x * BN;   // col tile (0..15)
    const int tid = threadIdx.x;
    const int tr = tid >> 4;          // 0..15
    const int tc = tid & 15;          // 0..15

    float acc[TM][TN] = {};

    const float* Aptr = g_embn + (size_t)r0 * Dd;
    const float* Bptr = g_cent + (size_t)c0 * Dd;
    const int lr = tid >> 1;          // 0..127 (tile row to load)
    const int lk = (tid & 1) * 4;     // 0 or 4 (k sub-chunk)

    for (int k0 = 0; k0 < Dd; k0 += BK) {
        float4 a = *(const float4*)(Aptr + (size_t)lr * Dd + k0 + lk);
        float4 bv = *(const float4*)(Bptr + (size_t)lr * Dd + k0 + lk);
        As[lk + 0][lr] = a.x;  As[lk + 1][lr] = a.y;
        As[lk + 2][lr] = a.z;  As[lk + 3][lr] = a.w;
        Bs[lk + 0][lr] = bv.x; Bs[lk + 1][lr] = bv.y;
        Bs[lk + 2][lr] = bv.z; Bs[lk + 3][lr] = bv.w;
        __syncthreads();

#pragma unroll
        for (int k = 0; k < BK; k++) {
            float4 a0 = *(const float4*)&As[k][tr * TM];
            float4 a1 = *(const float4*)&As[k][tr * TM + 4];
            float4 b0 = *(const float4*)&Bs[k][tc * TN];
            float4 b1 = *(const float4*)&Bs[k][tc * TN + 4];
            float ra[TM] = {a0.x, a0.y, a0.z, a0.w, a1.x, a1.y, a1.z, a1.w};
            float rb[TN] = {b0.x, b0.y, b0.z, b0.w, b1.x, b1.y, b1.z, b1.w};
#pragma unroll
            for (int i = 0; i < TM; i++)
#pragma unroll
                for (int j = 0; j < TN; j++)
                    acc[i][j] = fmaf(ra[i], rb[j], acc[i][j]);
        }
        __syncthreads();
    }

    const float wabs = fabsf(*wp);
    const float b = *bp;
    const float shift = wabs + b;

#pragma unroll
    for (int i = 0; i < TM; i++) {
        const int r = r0 + tr * TM + i;
        const int posc = r / Mm;          // diagonal column for this row
        float rs = 0.f;
#pragma unroll
        for (int j = 0; j < TN; j++) {
            const int c = c0 + tc * TN + j;
            const float sim = fmaf(wabs, acc[i][j], b);
            rs += __expf(sim - shift);
            if (c == posc) g_pos[r] = sim;  // written by exactly one block/row
        }
        // reduce across the 16 threads owning this row (16-lane groups in warp)
#pragma unroll
        for (int off = 8; off > 0; off >>= 1)
            rs += __shfl_xor_sync(0xffffffffu, rs, off);
        if (tc == 0) atomicAdd(&g_rowsum[r], rs);
    }
}

// ---------------------------------------------------------------------------
// Kernel 3: final reduction. loss = mean_r( log(rowsum[r]) + shift - pos[r] )
// ---------------------------------------------------------------------------
__global__ void loss_kernel(const float* __restrict__ wp,
                            const float* __restrict__ bp,
                            float* __restrict__ out) {
    __shared__ float red[256];
    const float wabs = fabsf(*wp);
    const float shift = wabs + *bp;
    float s = 0.f;
    for (int r = threadIdx.x; r < ROWS; r += 256)
        s += logf(g_rowsum[r]) + shift - g_pos[r];
    red[threadIdx.x] = s;
    __syncthreads();
    for (int off = 128; off > 0; off >>= 1) {
        if (threadIdx.x < off) red[threadIdx.x] += red[threadIdx.x + off];
        __syncthreads();
    }
    if (threadIdx.x == 0) out[0] = red[0] / (float)ROWS;
}

// ---------------------------------------------------------------------------
extern "C" void kernel_launch(void* const* d_in, const int* in_sizes, int n_in,
                              void* d_out, int out_size) {
    const float* emb = (const float*)d_in[0];  // (2048, 10, 256) fp32
    const float* w   = (const float*)d_in[1];  // scalar
    const float* b   = (const float*)d_in[2];  // scalar
    float* out = (float*)d_out;                // scalar loss

    prep_kernel<<<Nn, 256>>>(emb);
    gemm_lse_kernel<<<dim3(Nn / 128, ROWS / 128), 256>>>(w, b);
    loss_kernel<<<1, 256>>>(w, b, out);
}

// round 3
// speedup vs baseline: 5.4896x; 5.4896x over previous
#include <cuda_runtime.h>
#include <cuda_bf16.h>
#include <cstdint>

#define Nn 2048
#define Mm 10
#define Dd 256
#define ROWS (Nn * Mm)      // 20480

// ---------------------------------------------------------------------------
// Scratch (device globals; no allocation allowed)
// ---------------------------------------------------------------------------
__device__ __align__(16) __nv_bfloat16 g_A[(size_t)ROWS * Dd];  // normalized emb, bf16
__device__ __align__(16) __nv_bfloat16 g_B[(size_t)Nn * Dd];    // normalized centroids, bf16
__device__ float g_rowsum[ROWS];
__device__ float g_pos[ROWS];

__device__ __forceinline__ uint32_t smem_u32(const void* p) {
    uint32_t a;
    asm("{ .reg .u64 t; cvta.to.shared.u64 t, %1; cvt.u32.u64 %0, t; }" : "=r"(a) : "l"(p));
    return a;
}
__device__ __forceinline__ void cpa16(uint32_t dst, const void* src) {
    asm volatile("cp.async.cg.shared.global [%0], [%1], 16;" :: "r"(dst), "l"(src));
}
__device__ __forceinline__ void ldm_x4(uint32_t* r, uint32_t addr) {
    asm volatile("ldmatrix.sync.aligned.m8n8.x4.shared.b16 {%0,%1,%2,%3}, [%4];"
                 : "=r"(r[0]), "=r"(r[1]), "=r"(r[2]), "=r"(r[3]) : "r"(addr));
}
__device__ __forceinline__ void mma_bf16(float* c, const uint32_t* a,
                                         uint32_t b0, uint32_t b1) {
    asm volatile(
        "mma.sync.aligned.m16n8k16.row.col.f32.bf16.bf16.f32 "
        "{%0,%1,%2,%3}, {%4,%5,%6,%7}, {%8,%9}, {%0,%1,%2,%3};"
        : "+f"(c[0]), "+f"(c[1]), "+f"(c[2]), "+f"(c[3])
        : "r"(a[0]), "r"(a[1]), "r"(a[2]), "r"(a[3]), "r"(b0), "r"(b1));
}

// ---------------------------------------------------------------------------
// Kernel 1: prep. One block per speaker n, 320 threads (warp m = utterance m).
// ---------------------------------------------------------------------------
__global__ void __launch_bounds__(320) prep_kernel(const float* __restrict__ emb) {
    const int n = blockIdx.x;
    const int tid = threadIdx.x;
    const int w = tid >> 5, lane = tid & 31;
    __shared__ float sv[Mm][Dd];
    __shared__ float warp_red[8];
    __shared__ float cnorm;

    {   // per-utterance L2 normalize -> bf16
        const float* src = emb + ((size_t)n * Mm + w) * Dd;
        float4 x0 = *(const float4*)(src + lane * 4);
        float4 x1 = *(const float4*)(src + 128 + lane * 4);
        float ss = x0.x * x0.x + x0.y * x0.y + x0.z * x0.z + x0.w * x0.w
                 + x1.x * x1.x + x1.y * x1.y + x1.z * x1.z + x1.w * x1.w;
#pragma unroll
        for (int off = 16; off > 0; off >>= 1) ss += __shfl_xor_sync(0xffffffffu, ss, off);
        float sc = 1.f / fmaxf(sqrtf(ss), 1e-12f);
        __nv_bfloat16* dst = g_A + (size_t)(n * Mm + w) * Dd;
        __nv_bfloat162 p0 = __floats2bfloat162_rn(x0.x * sc, x0.y * sc);
        __nv_bfloat162 p1 = __floats2bfloat162_rn(x0.z * sc, x0.w * sc);
        __nv_bfloat162 p2 = __floats2bfloat162_rn(x1.x * sc, x1.y * sc);
        __nv_bfloat162 p3 = __floats2bfloat162_rn(x1.z * sc, x1.w * sc);
        uint2 v0{*(uint32_t*)&p0, *(uint32_t*)&p1};
        uint2 v1{*(uint32_t*)&p2, *(uint32_t*)&p3};
        *(uint2*)(dst + lane * 4) = v0;
        *(uint2*)(dst + 128 + lane * 4) = v1;
        *(float4*)&sv[w][lane * 4] = x0;
        *(float4*)&sv[w][128 + lane * 4] = x1;
    }
    __syncthreads();

    // centroid = l2norm(sum_m emb) (scale-invariant; skip /M)
    float s = 0.f;
    if (tid < Dd) {
#pragma unroll
        for (int m = 0; m < Mm; m++) s += sv[m][tid];
        float ss = s * s;
#pragma unroll
        for (int off = 16; off > 0; off >>= 1) ss += __shfl_xor_sync(0xffffffffu, ss, off);
        if (lane == 0) warp_red[tid >> 5] = ss;
    }
    __syncthreads();
    if (tid == 0) {
        float t = 0.f;
#pragma unroll
        for (int i = 0; i < 8; i++) t += warp_red[i];
        cnorm = fmaxf(sqrtf(t), 1e-12f);
    }
    __syncthreads();
    if (tid < Dd) g_B[(size_t)n * Dd + tid] = __float2bfloat16(s / cnorm);
    if (tid < Mm) g_rowsum[n * Mm + tid] = 0.f;   // graph-replay-safe zeroing
}

// ---------------------------------------------------------------------------
// Kernel 2: HMMA bf16 GEMM (BM=128, BN=128, BK=32) + fused logsumexp epilogue.
// 8 warps: wm = wid&3 (32-row slice), wn = wid>>2 (64-col slice).
// Smem rows padded to 40 elems (80B) -> conflict-free ldmatrix.
// ---------------------------------------------------------------------------
#define BK 32
#define SSTR 40     // padded row stride in elems
#define NCHUNK (Dd / BK)   // 8

__global__ void __launch_bounds__(256, 2)
gemm_lse_kernel(const float* __restrict__ wp, const float* __restrict__ bp) {
    __shared__ __nv_bfloat16 As[2][128 * SSTR];
    __shared__ __nv_bfloat16 Bs[2][128 * SSTR];

    const int tid = threadIdx.x;
    const int wid = tid >> 5, lane = tid & 31;
    const int wm = wid & 3, wn = wid >> 2;
    const int r0 = blockIdx.y * 128;
    const int c0 = blockIdx.x * 128;

    const uint32_t as0 = smem_u32(&As[0][0]);
    const uint32_t bs0 = smem_u32(&Bs[0][0]);
    const int ldrow = tid >> 2;       // 0..63 (two iters -> 128 rows)
    const int ldch = tid & 3;         // 16B chunk within 64B row

    auto load_chunk = [&](int c, int stg) {
        const __nv_bfloat16* gA = g_A + (size_t)(r0 + ldrow) * Dd + c * BK + ldch * 8;
        const __nv_bfloat16* gB = g_B + (size_t)(c0 + ldrow) * Dd + c * BK + ldch * 8;
        uint32_t da = as0 + stg * (128 * SSTR * 2) + ldrow * (SSTR * 2) + ldch * 16;
        uint32_t db = bs0 + stg * (128 * SSTR * 2) + ldrow * (SSTR * 2) + ldch * 16;
        cpa16(da, gA);
        cpa16(da + 64 * SSTR * 2, gA + (size_t)64 * Dd);
        cpa16(db, gB);
        cpa16(db + 64 * SSTR * 2, gB + (size_t)64 * Dd);
        asm volatile("cp.async.commit_group;" ::: "memory");
    };

    float acc[2][8][4] = {};

    load_chunk(0, 0);
#pragma unroll
    for (int c = 0; c < NCHUNK; c++) {
        if (c + 1 < NCHUNK) load_chunk(c + 1, (c + 1) & 1);
        if (c + 1 < NCHUNK) asm volatile("cp.async.wait_group 1;" ::: "memory");
        else                asm volatile("cp.async.wait_group 0;" ::: "memory");
        __syncthreads();

        const uint32_t ab = as0 + (c & 1) * (128 * SSTR * 2);
        const uint32_t bb = bs0 + (c & 1) * (128 * SSTR * 2);
#pragma unroll
        for (int ks = 0; ks < 2; ks++) {
            const int k0 = ks * 16;
            uint32_t a[2][4];
#pragma unroll
            for (int mt = 0; mt < 2; mt++) {
                int row = wm * 32 + mt * 16 + (lane & 15);
                int col = k0 + (lane >> 4) * 8;
                ldm_x4(a[mt], ab + row * (SSTR * 2) + col * 2);
            }
            uint32_t b[4][4];
#pragma unroll
            for (int ng = 0; ng < 4; ng++) {
                int row = wn * 64 + ng * 16 + (lane & 7) + (lane >> 4) * 8;
                int col = k0 + ((lane >> 3) & 1) * 8;
                ldm_x4(b[ng], bb + row * (SSTR * 2) + col * 2);
            }
#pragma unroll
            for (int mt = 0; mt < 2; mt++)
#pragma unroll
                for (int nt = 0; nt < 8; nt++)
                    mma_bf16(acc[mt][nt], a[mt],
                             b[nt >> 1][(nt & 1) * 2], b[nt >> 1][(nt & 1) * 2 + 1]);
        }
        __syncthreads();
    }

    // ---- fused epilogue: sim = |w|*cos + b; rowsum += exp(sim - shift) ----
    const float wabs = fabsf(*wp);
    const float bias = *bp;
    const float shift = wabs + bias;
    const int q = lane >> 2, qi = lane & 3;
    const int cbase = c0 + wn * 64;

#pragma unroll
    for (int mt = 0; mt < 2; mt++) {
        const int rowA = r0 + wm * 32 + mt * 16 + q;
        const int rowB = rowA + 8;
        const int posA = rowA / Mm, posB = rowB / Mm;
        float sA = 0.f, sB = 0.f;
#pragma unroll
        for (int nt = 0; nt < 8; nt++) {
            const int col = cbase + nt * 8 + qi * 2;
            float s0 = fmaf(wabs, acc[mt][nt][0], bias);
            float s1 = fmaf(wabs, acc[mt][nt][1], bias);
            float s2 = fmaf(wabs, acc[mt][nt][2], bias);
            float s3 = fmaf(wabs, acc[mt][nt][3], bias);
            sA += __expf(s0 - shift) + __expf(s1 - shift);
            sB += __expf(s2 - shift) + __expf(s3 - shift);
            if (col == posA) g_pos[rowA] = s0;
            if (col + 1 == posA) g_pos[rowA] = s1;
            if (col == posB) g_pos[rowB] = s2;
            if (col + 1 == posB) g_pos[rowB] = s3;
        }
#pragma unroll
        for (int off = 2; off > 0; off >>= 1) {
            sA += __shfl_xor_sync(0xffffffffu, sA, off);
            sB += __shfl_xor_sync(0xffffffffu, sB, off);
        }
        if (qi == 0) {
            atomicAdd(&g_rowsum[rowA], sA);
            atomicAdd(&g_rowsum[rowB], sB);
        }
    }
}

// ---------------------------------------------------------------------------
// Kernel 3: loss = mean_r( log(rowsum[r]) + shift - pos[r] )
// ---------------------------------------------------------------------------
__global__ void loss_kernel(const float* __restrict__ wp,
                            const float* __restrict__ bp,
                            float* __restrict__ out) {
    __shared__ float red[256];
    const float shift = fabsf(*wp) + *bp;
    float s = 0.f;
    for (int r = threadIdx.x; r < ROWS; r += 256)
        s += logf(g_rowsum[r]) + shift - g_pos[r];
    red[threadIdx.x] = s;
    __syncthreads();
    for (int off = 128; off > 0; off >>= 1) {
        if (threadIdx.x < off) red[threadIdx.x] += red[threadIdx.x + off];
        __syncthreads();
    }
    if (threadIdx.x == 0) out[0] = red[0] / (float)ROWS;
}

// ---------------------------------------------------------------------------
extern "C" void kernel_launch(void* const* d_in, const int* in_sizes, int n_in,
                              void* d_out, int out_size) {
    const float* emb = (const float*)d_in[0];
    const float* w   = (const float*)d_in[1];
    const float* b   = (const float*)d_in[2];
    float* out = (float*)d_out;

    prep_kernel<<<Nn, 320>>>(emb);
    gemm_lse_kernel<<<dim3(Nn / 128, ROWS / 128), 256>>>(w, b);
    loss_kernel<<<1, 256>>>(w, b, out);
}

// round 4
// speedup vs baseline: 5.6754x; 1.0338x over previous
#include <cuda_runtime.h>
#include <cuda_bf16.h>
#include <cstdint>

#define Nn 2048
#define Mm 10
#define Dd 256
#define ROWS (Nn * Mm)      // 20480

// ---------------------------------------------------------------------------
// Scratch (device globals; no allocation allowed)
// ---------------------------------------------------------------------------
__device__ __align__(16) __nv_bfloat16 g_A[(size_t)ROWS * Dd];  // normalized emb, bf16
__device__ __align__(16) __nv_bfloat16 g_B[(size_t)Nn * Dd];    // normalized centroids, bf16
__device__ float g_rowsum[ROWS];
__device__ float g_pos[ROWS];   // stores t = |w|*(cos-1); shift cancels in lse-pos

__device__ __forceinline__ uint32_t smem_u32(const void* p) {
    uint32_t a;
    asm("{ .reg .u64 t; cvta.to.shared.u64 t, %1; cvt.u32.u64 %0, t; }" : "=r"(a) : "l"(p));
    return a;
}
__device__ __forceinline__ void cpa16(uint32_t dst, const void* src) {
    asm volatile("cp.async.cg.shared.global [%0], [%1], 16;" :: "r"(dst), "l"(src));
}
__device__ __forceinline__ void ldm_x4(uint32_t* r, uint32_t addr) {
    asm volatile("ldmatrix.sync.aligned.m8n8.x4.shared.b16 {%0,%1,%2,%3}, [%4];"
                 : "=r"(r[0]), "=r"(r[1]), "=r"(r[2]), "=r"(r[3]) : "r"(addr));
}
__device__ __forceinline__ void mma_bf16(float* c, const uint32_t* a,
                                         uint32_t b0, uint32_t b1) {
    asm volatile(
        "mma.sync.aligned.m16n8k16.row.col.f32.bf16.bf16.f32 "
        "{%0,%1,%2,%3}, {%4,%5,%6,%7}, {%8,%9}, {%0,%1,%2,%3};"
        : "+f"(c[0]), "+f"(c[1]), "+f"(c[2]), "+f"(c[3])
        : "r"(a[0]), "r"(a[1]), "r"(a[2]), "r"(a[3]), "r"(b0), "r"(b1));
}

// ---------------------------------------------------------------------------
// Kernel 1: prep. One block per speaker n, 320 threads (warp m = utterance m).
// ---------------------------------------------------------------------------
__global__ void __launch_bounds__(320) prep_kernel(const float* __restrict__ emb) {
    const int n = blockIdx.x;
    const int tid = threadIdx.x;
    const int w = tid >> 5, lane = tid & 31;
    __shared__ float sv[Mm][Dd];
    __shared__ float warp_red[8];
    __shared__ float cnorm;

    {   // per-utterance L2 normalize -> bf16
        const float* src = emb + ((size_t)n * Mm + w) * Dd;
        float4 x0 = *(const float4*)(src + lane * 4);
        float4 x1 = *(const float4*)(src + 128 + lane * 4);
        float ss = x0.x * x0.x + x0.y * x0.y + x0.z * x0.z + x0.w * x0.w
                 + x1.x * x1.x + x1.y * x1.y + x1.z * x1.z + x1.w * x1.w;
#pragma unroll
        for (int off = 16; off > 0; off >>= 1) ss += __shfl_xor_sync(0xffffffffu, ss, off);
        float sc = 1.f / fmaxf(sqrtf(ss), 1e-12f);
        __nv_bfloat16* dst = g_A + (size_t)(n * Mm + w) * Dd;
        __nv_bfloat162 p0 = __floats2bfloat162_rn(x0.x * sc, x0.y * sc);
        __nv_bfloat162 p1 = __floats2bfloat162_rn(x0.z * sc, x0.w * sc);
        __nv_bfloat162 p2 = __floats2bfloat162_rn(x1.x * sc, x1.y * sc);
        __nv_bfloat162 p3 = __floats2bfloat162_rn(x1.z * sc, x1.w * sc);
        uint2 v0{*(uint32_t*)&p0, *(uint32_t*)&p1};
        uint2 v1{*(uint32_t*)&p2, *(uint32_t*)&p3};
        *(uint2*)(dst + lane * 4) = v0;
        *(uint2*)(dst + 128 + lane * 4) = v1;
        *(float4*)&sv[w][lane * 4] = x0;
        *(float4*)&sv[w][128 + lane * 4] = x1;
    }
    __syncthreads();

    // centroid = l2norm(sum_m emb) (scale-invariant; skip /M)
    float s = 0.f;
    if (tid < Dd) {
#pragma unroll
        for (int m = 0; m < Mm; m++) s += sv[m][tid];
        float ss = s * s;
#pragma unroll
        for (int off = 16; off > 0; off >>= 1) ss += __shfl_xor_sync(0xffffffffu, ss, off);
        if (lane == 0) warp_red[tid >> 5] = ss;
    }
    __syncthreads();
    if (tid == 0) {
        float t = 0.f;
#pragma unroll
        for (int i = 0; i < 8; i++) t += warp_red[i];
        cnorm = fmaxf(sqrtf(t), 1e-12f);
    }
    __syncthreads();
    if (tid < Dd) g_B[(size_t)n * Dd + tid] = __float2bfloat16(s / cnorm);
    if (tid < Mm) g_rowsum[n * Mm + tid] = 0.f;   // graph-replay-safe zeroing
}

// ---------------------------------------------------------------------------
// Kernel 2: HMMA bf16 GEMM, CTA tile 128x256, warp tile 64x64 (2x4 warps),
// BK=32, 4-stage cp.async pipeline, ONE __syncthreads per chunk.
// Fused epilogue: rowsum += exp(|w|*(cos-1)); pos stores |w|*(cos-1).
// ---------------------------------------------------------------------------
#define BK 32
#define SSTR 40                       // padded row stride (elems); 80B
#define NCHUNK (Dd / BK)              // 8
#define STGA (128 * SSTR * 2)         // 10240 B per A stage
#define STGB (256 * SSTR * 2)         // 20480 B per B stage
#define SMEM_BYTES (4 * (STGA + STGB))  // 122880

__global__ void __launch_bounds__(256)
gemm_lse_kernel(const float* __restrict__ wp, const float* __restrict__ bp) {
    extern __shared__ char smem[];
    const uint32_t as0 = smem_u32(smem);
    const uint32_t bs0 = as0 + 4 * STGA;

    const int tid = threadIdx.x;
    const int wid = tid >> 5, lane = tid & 31;
    const int wm = wid >> 2;          // 0..1  (64-row slice)
    const int wn = wid & 3;           // 0..3  (64-col slice)
    const int r0 = blockIdx.y * 128;
    const int c0 = blockIdx.x * 256;

    const int lrow = tid >> 2;        // 0..63
    const int lquad = tid & 3;        // 16B quad within 64B of row-chunk

    auto load_chunk = [&](int c, int stg) {
        // A: 128 rows x 32 cols (8KB): 512 16B loads, 2 per thread
#pragma unroll
        for (int i = 0; i < 2; i++) {
            int row = lrow + i * 64;
            cpa16(as0 + stg * STGA + row * (SSTR * 2) + lquad * 16,
                  g_A + (size_t)(r0 + row) * Dd + c * BK + lquad * 8);
        }
        // B: 256 rows x 32 cols (16KB): 1024 16B loads, 4 per thread
#pragma unroll
        for (int i = 0; i < 4; i++) {
            int row = lrow + i * 64;
            cpa16(bs0 + stg * STGB + row * (SSTR * 2) + lquad * 16,
                  g_B + (size_t)(c0 + row) * Dd + c * BK + lquad * 8);
        }
        asm volatile("cp.async.commit_group;" ::: "memory");
    };

    float acc[4][8][4] = {};

    // prologue: chunks 0..2 -> stages 0..2
    load_chunk(0, 0);
    load_chunk(1, 1);
    load_chunk(2, 2);

#pragma unroll
    for (int c = 0; c < NCHUNK; c++) {
        if (c <= 5)      asm volatile("cp.async.wait_group 2;" ::: "memory");
        else if (c == 6) asm volatile("cp.async.wait_group 1;" ::: "memory");
        else             asm volatile("cp.async.wait_group 0;" ::: "memory");
        __syncthreads();
        if (c + 3 < NCHUNK) load_chunk(c + 3, (c + 3) & 3);

        const uint32_t ab = as0 + (c & 3) * STGA;
        const uint32_t bb = bs0 + (c & 3) * STGB;
#pragma unroll
        for (int ks = 0; ks < 2; ks++) {
            const int k0 = ks * 16;
            uint32_t a[4][4];
#pragma unroll
            for (int mt = 0; mt < 4; mt++) {
                int row = wm * 64 + mt * 16 + (lane & 15);
                int col = k0 + (lane >> 4) * 8;
                ldm_x4(a[mt], ab + row * (SSTR * 2) + col * 2);
            }
            uint32_t b[4][4];
#pragma unroll
            for (int ng = 0; ng < 4; ng++) {
                int row = wn * 64 + ng * 16 + (lane & 7) + (lane >> 4) * 8;
                int col = k0 + ((lane >> 3) & 1) * 8;
                ldm_x4(b[ng], bb + row * (SSTR * 2) + col * 2);
            }
#pragma unroll
            for (int mt = 0; mt < 4; mt++)
#pragma unroll
                for (int nt = 0; nt < 8; nt++)
                    mma_bf16(acc[mt][nt], a[mt],
                             b[nt >> 1][(nt & 1) * 2], b[nt >> 1][(nt & 1) * 2 + 1]);
        }
    }

    // ---- fused epilogue: t = |w|*(cos-1); rowsum += exp(t); pos = t ----
    const float wabs = fabsf(*wp);
    const float nw = -wabs;
    const int q = lane >> 2, qi = lane & 3;
    const int cbase = c0 + wn * 64;

#pragma unroll
    for (int mt = 0; mt < 4; mt++) {
        const int rowA = r0 + wm * 64 + mt * 16 + q;
        const int rowB = rowA + 8;
        const int posA = rowA / Mm, posB = rowB / Mm;
        float sA = 0.f, sB = 0.f;
#pragma unroll
        for (int nt = 0; nt < 8; nt++) {
            const int col = cbase + nt * 8 + qi * 2;
            float t0 = fmaf(wabs, acc[mt][nt][0], nw);
            float t1 = fmaf(wabs, acc[mt][nt][1], nw);
            float t2 = fmaf(wabs, acc[mt][nt][2], nw);
            float t3 = fmaf(wabs, acc[mt][nt][3], nw);
            sA += __expf(t0) + __expf(t1);
            sB += __expf(t2) + __expf(t3);
            if (col == posA) g_pos[rowA] = t0;
            if (col + 1 == posA) g_pos[rowA] = t1;
            if (col == posB) g_pos[rowB] = t2;
            if (col + 1 == posB) g_pos[rowB] = t3;
        }
#pragma unroll
        for (int off = 2; off > 0; off >>= 1) {
            sA += __shfl_xor_sync(0xffffffffu, sA, off);
            sB += __shfl_xor_sync(0xffffffffu, sB, off);
        }
        if (qi == 0) {
            atomicAdd(&g_rowsum[rowA], sA);
            atomicAdd(&g_rowsum[rowB], sB);
        }
    }
}

// ---------------------------------------------------------------------------
// Kernel 3: loss = mean_r( log(rowsum[r]) - pos_t[r] )   (shift cancels)
// ---------------------------------------------------------------------------
__global__ void loss_kernel(float* __restrict__ out) {
    __shared__ float red[256];
    float s = 0.f;
    for (int r = threadIdx.x; r < ROWS; r += 256)
        s += __logf(g_rowsum[r]) - g_pos[r];
    red[threadIdx.x] = s;
    __syncthreads();
    for (int off = 128; off > 0; off >>= 1) {
        if (threadIdx.x < off) red[threadIdx.x] += red[threadIdx.x + off];
        __syncthreads();
    }
    if (threadIdx.x == 0) out[0] = red[0] / (float)ROWS;
}

// ---------------------------------------------------------------------------
extern "C" void kernel_launch(void* const* d_in, const int* in_sizes, int n_in,
                              void* d_out, int out_size) {
    const float* emb = (const float*)d_in[0];
    const float* w   = (const float*)d_in[1];
    const float* b   = (const float*)d_in[2];
    (void)b;
    float* out = (float*)d_out;

    static int smem_set = 0;
    if (!smem_set) {
        cudaFuncSetAttribute(gemm_lse_kernel,
                             cudaFuncAttributeMaxDynamicSharedMemorySize, SMEM_BYTES);
        smem_set = 1;
    }

    prep_kernel<<<Nn, 320>>>(emb);
    gemm_lse_kernel<<<dim3(Nn / 256, ROWS / 128), 256, SMEM_BYTES>>>(w, b);
    loss_kernel<<<1, 256>>>(out);
}

// round 5
// speedup vs baseline: 6.2093x; 1.0941x over previous
#include <cuda_runtime.h>
#include <cuda_bf16.h>
#include <cstdint>

#define Nn 2048
#define Mm 10
#define Dd 256
#define ROWS (Nn * Mm)      // 20480

// ---------------------------------------------------------------------------
// Scratch (device globals; no allocation allowed)
// ---------------------------------------------------------------------------
__device__ __align__(16) __nv_bfloat16 g_A[(size_t)ROWS * Dd];  // normalized emb, bf16
__device__ __align__(16) __nv_bfloat16 g_B[(size_t)Nn * Dd];    // normalized centroids, bf16
__device__ float g_rowsum[ROWS];
__device__ float g_pos[ROWS];   // stores t = |w|*(cos-1); shift cancels in lse-pos

__device__ __forceinline__ uint32_t smem_u32(const void* p) {
    uint32_t a;
    asm("{ .reg .u64 t; cvta.to.shared.u64 t, %1; cvt.u32.u64 %0, t; }" : "=r"(a) : "l"(p));
    return a;
}
__device__ __forceinline__ void cpa16(uint32_t dst, const void* src) {
    asm volatile("cp.async.cg.shared.global [%0], [%1], 16;" :: "r"(dst), "l"(src));
}
__device__ __forceinline__ void ldm_x4(uint32_t* r, uint32_t addr) {
    asm volatile("ldmatrix.sync.aligned.m8n8.x4.shared.b16 {%0,%1,%2,%3}, [%4];"
                 : "=r"(r[0]), "=r"(r[1]), "=r"(r[2]), "=r"(r[3]) : "r"(addr));
}
__device__ __forceinline__ void mma_bf16(float* c, const uint32_t* a,
                                         uint32_t b0, uint32_t b1) {
    asm volatile(
        "mma.sync.aligned.m16n8k16.row.col.f32.bf16.bf16.f32 "
        "{%0,%1,%2,%3}, {%4,%5,%6,%7}, {%8,%9}, {%0,%1,%2,%3};"
        : "+f"(c[0]), "+f"(c[1]), "+f"(c[2]), "+f"(c[3])
        : "r"(a[0]), "r"(a[1]), "r"(a[2]), "r"(a[3]), "r"(b0), "r"(b1));
}

// ---------------------------------------------------------------------------
// Kernel 1: prep. One block per speaker n, 320 threads (warp m = utterance m).
// ---------------------------------------------------------------------------
__global__ void __launch_bounds__(320) prep_kernel(const float* __restrict__ emb) {
    const int n = blockIdx.x;
    const int tid = threadIdx.x;
    const int w = tid >> 5, lane = tid & 31;
    __shared__ float sv[Mm][Dd];
    __shared__ float warp_red[8];
    __shared__ float cnorm;

    {   // per-utterance L2 normalize -> bf16
        const float* src = emb + ((size_t)n * Mm + w) * Dd;
        float4 x0 = *(const float4*)(src + lane * 4);
        float4 x1 = *(const float4*)(src + 128 + lane * 4);
        float ss = x0.x * x0.x + x0.y * x0.y + x0.z * x0.z + x0.w * x0.w
                 + x1.x * x1.x + x1.y * x1.y + x1.z * x1.z + x1.w * x1.w;
#pragma unroll
        for (int off = 16; off > 0; off >>= 1) ss += __shfl_xor_sync(0xffffffffu, ss, off);
        float sc = 1.f / fmaxf(sqrtf(ss), 1e-12f);
        __nv_bfloat16* dst = g_A + (size_t)(n * Mm + w) * Dd;
        __nv_bfloat162 p0 = __floats2bfloat162_rn(x0.x * sc, x0.y * sc);
        __nv_bfloat162 p1 = __floats2bfloat162_rn(x0.z * sc, x0.w * sc);
        __nv_bfloat162 p2 = __floats2bfloat162_rn(x1.x * sc, x1.y * sc);
        __nv_bfloat162 p3 = __floats2bfloat162_rn(x1.z * sc, x1.w * sc);
        uint2 v0{*(uint32_t*)&p0, *(uint32_t*)&p1};
        uint2 v1{*(uint32_t*)&p2, *(uint32_t*)&p3};
        *(uint2*)(dst + lane * 4) = v0;
        *(uint2*)(dst + 128 + lane * 4) = v1;
        *(float4*)&sv[w][lane * 4] = x0;
        *(float4*)&sv[w][128 + lane * 4] = x1;
    }
    __syncthreads();

    // centroid = l2norm(sum_m emb) (scale-invariant; skip /M)
    float s = 0.f;
    if (tid < Dd) {
#pragma unroll
        for (int m = 0; m < Mm; m++) s += sv[m][tid];
        float ss = s * s;
#pragma unroll
        for (int off = 16; off > 0; off >>= 1) ss += __shfl_xor_sync(0xffffffffu, ss, off);
        if (lane == 0) warp_red[tid >> 5] = ss;
    }
    __syncthreads();
    if (tid == 0) {
        float t = 0.f;
#pragma unroll
        for (int i = 0; i < 8; i++) t += warp_red[i];
        cnorm = fmaxf(sqrtf(t), 1e-12f);
    }
    __syncthreads();
    if (tid < Dd) g_B[(size_t)n * Dd + tid] = __float2bfloat16(s / cnorm);
    if (tid < Mm) g_rowsum[n * Mm + tid] = 0.f;   // graph-replay-safe zeroing
}

// ---------------------------------------------------------------------------
// Kernel 2: HMMA bf16 GEMM, CTA tile 128x128, warp tile 64x32 (2x4 warps),
// BK=32, 3-stage cp.async pipeline, one __syncthreads per chunk.
// Smem = 61,440 B -> 2 CTAs/SM (16 warps/SM) for latency hiding.
// Fused epilogue: rowsum += exp(|w|*(cos-1)); pos stores |w|*(cos-1).
// ---------------------------------------------------------------------------
#define BK 32
#define SSTR 40                       // padded row stride (elems); 80B
#define NCHUNK (Dd / BK)              // 8
#define STG (128 * SSTR * 2)          // 10240 B per tile stage
#define SMEM_BYTES (3 * 2 * STG)      // 61440

__global__ void __launch_bounds__(256, 2)
gemm_lse_kernel(const float* __restrict__ wp, const float* __restrict__ bp) {
    extern __shared__ char smem[];
    const uint32_t as0 = smem_u32(smem);
    const uint32_t bs0 = as0 + 3 * STG;

    const int tid = threadIdx.x;
    const int wid = tid >> 5, lane = tid & 31;
    const int wm = wid & 1;           // 0..1  (64-row slice)
    const int wn = wid >> 1;          // 0..3  (32-col slice)
    const int r0 = blockIdx.y * 128;
    const int c0 = blockIdx.x * 128;

    const int lrow = tid >> 2;        // 0..63
    const int lquad = tid & 3;        // 16B quad within 64B of row-chunk

    auto load_chunk = [&](int c, int stg) {
        // A and B: each 128 rows x 32 cols (8KB): 512 16B loads, 2 per thread
#pragma unroll
        for (int i = 0; i < 2; i++) {
            int row = lrow + i * 64;
            cpa16(as0 + stg * STG + row * (SSTR * 2) + lquad * 16,
                  g_A + (size_t)(r0 + row) * Dd + c * BK + lquad * 8);
            cpa16(bs0 + stg * STG + row * (SSTR * 2) + lquad * 16,
                  g_B + (size_t)(c0 + row) * Dd + c * BK + lquad * 8);
        }
        asm volatile("cp.async.commit_group;" ::: "memory");
    };

    float acc[4][4][4] = {};

    // prologue: chunks 0,1 -> stages 0,1
    load_chunk(0, 0);
    load_chunk(1, 1);

#pragma unroll
    for (int c = 0; c < NCHUNK; c++) {
        if (c <= 6) asm volatile("cp.async.wait_group 1;" ::: "memory");
        else        asm volatile("cp.async.wait_group 0;" ::: "memory");
        __syncthreads();
        if (c + 2 < NCHUNK) load_chunk(c + 2, (c + 2) % 3);

        const uint32_t ab = as0 + (c % 3) * STG;
        const uint32_t bb = bs0 + (c % 3) * STG;
#pragma unroll
        for (int ks = 0; ks < 2; ks++) {
            const int k0 = ks * 16;
            uint32_t a[4][4];
#pragma unroll
            for (int mt = 0; mt < 4; mt++) {
                int row = wm * 64 + mt * 16 + (lane & 15);
                int col = k0 + (lane >> 4) * 8;
                ldm_x4(a[mt], ab + row * (SSTR * 2) + col * 2);
            }
            uint32_t b[2][4];
#pragma unroll
            for (int ng = 0; ng < 2; ng++) {
                int row = wn * 32 + ng * 16 + (lane & 7) + (lane >> 4) * 8;
                int col = k0 + ((lane >> 3) & 1) * 8;
                ldm_x4(b[ng], bb + row * (SSTR * 2) + col * 2);
            }
#pragma unroll
            for (int mt = 0; mt < 4; mt++)
#pragma unroll
                for (int nt = 0; nt < 4; nt++)
                    mma_bf16(acc[mt][nt], a[mt],
                             b[nt >> 1][(nt & 1) * 2], b[nt >> 1][(nt & 1) * 2 + 1]);
        }
    }

    // ---- fused epilogue: t = |w|*(cos-1); rowsum += exp(t); pos = t ----
    const float wabs = fabsf(*wp);
    const float nw = -wabs;
    const int q = lane >> 2, qi = lane & 3;
    const int cbase = c0 + wn * 32;

#pragma unroll
    for (int mt = 0; mt < 4; mt++) {
        const int rowA = r0 + wm * 64 + mt * 16 + q;
        const int rowB = rowA + 8;
        const int posA = rowA / Mm, posB = rowB / Mm;
        float sA = 0.f, sB = 0.f;
#pragma unroll
        for (int nt = 0; nt < 4; nt++) {
            const int col = cbase + nt * 8 + qi * 2;
            float t0 = fmaf(wabs, acc[mt][nt][0], nw);
            float t1 = fmaf(wabs, acc[mt][nt][1], nw);
            float t2 = fmaf(wabs, acc[mt][nt][2], nw);
            float t3 = fmaf(wabs, acc[mt][nt][3], nw);
            sA += __expf(t0) + __expf(t1);
            sB += __expf(t2) + __expf(t3);
            if (col == posA) g_pos[rowA] = t0;
            if (col + 1 == posA) g_pos[rowA] = t1;
            if (col == posB) g_pos[rowB] = t2;
            if (col + 1 == posB) g_pos[rowB] = t3;
        }
#pragma unroll
        for (int off = 2; off > 0; off >>= 1) {
            sA += __shfl_xor_sync(0xffffffffu, sA, off);
            sB += __shfl_xor_sync(0xffffffffu, sB, off);
        }
        if (qi == 0) {
            atomicAdd(&g_rowsum[rowA], sA);
            atomicAdd(&g_rowsum[rowB], sB);
        }
    }
}

// ---------------------------------------------------------------------------
// Kernel 3: loss = mean_r( log(rowsum[r]) - pos_t[r] )   (shift cancels)
// ---------------------------------------------------------------------------
__global__ void loss_kernel(float* __restrict__ out) {
    __shared__ float red[256];
    float s = 0.f;
    for (int r = threadIdx.x; r < ROWS; r += 256)
        s += __logf(g_rowsum[r]) - g_pos[r];
    red[threadIdx.x] = s;
    __syncthreads();
    for (int off = 128; off > 0; off >>= 1) {
        if (threadIdx.x < off) red[threadIdx.x] += red[threadIdx.x + off];
        __syncthreads();
    }
    if (threadIdx.x == 0) out[0] = red[0] / (float)ROWS;
}

// ---------------------------------------------------------------------------
extern "C" void kernel_launch(void* const* d_in, const int* in_sizes, int n_in,
                              void* d_out, int out_size) {
    const float* emb = (const float*)d_in[0];
    const float* w   = (const float*)d_in[1];
    const float* b   = (const float*)d_in[2];
    (void)b;
    float* out = (float*)d_out;

    static int smem_set = 0;
    if (!smem_set) {
        cudaFuncSetAttribute(gemm_lse_kernel,
                             cudaFuncAttributeMaxDynamicSharedMemorySize, SMEM_BYTES);
        smem_set = 1;
    }

    prep_kernel<<<Nn, 320>>>(emb);
    gemm_lse_kernel<<<dim3(Nn / 128, ROWS / 128), 256, SMEM_BYTES>>>(w, b);
    loss_kernel<<<1, 256>>>(out);
}